// round 13
// baseline (speedup 1.0000x reference)
#include <cuda_runtime.h>
#include <cstdint>

#define NROWS 65536
#define KCODES 8192
#define DDIM 512

#define QSCALE 448.0f
#define INV2SS (2.0f / (QSCALE * QSCALE))

// ---------------- static device scratch ----------------
__device__ float g_zn[(size_t)NROWS * DDIM];       // normalized z (fp32)
__device__ float g_cb[(size_t)KCODES * DDIM];      // normalized codebook (fp32)
__device__ float g_ncb[KCODES];                    // ||cb||^2 (of rounded normalized row)
__device__ signed char g_a8[(size_t)NROWS * DDIM]; // int8(zn * QSCALE)
__device__ signed char g_b8[(size_t)KCODES * DDIM];// int8(cb * QSCALE)
__device__ unsigned long long g_part[(size_t)NROWS * 128]; // top4 per (row, 256-wide ntile)
__device__ int g_bestidx[NROWS];

// ---------------- helpers ----------------
__device__ __forceinline__ uint32_t smem_to_u32(const void* p) {
    uint32_t a;
    asm("{ .reg .u64 t; cvta.to.shared.u64 t, %1; cvt.u32.u64 %0, t; }" : "=r"(a) : "l"(p));
    return a;
}
#define SMEM_SWIZZLE_128B(o) ((o) ^ (((o) >> 3) & 0x70))

__device__ __forceinline__ void cp16(uint32_t dst, const void* src) {
    asm volatile("cp.async.cg.shared.global [%0], [%1], 16;" :: "r"(dst), "l"(src));
}
__device__ __forceinline__ void ldsm_x4(uint32_t* r, uint32_t addr) {
    asm volatile("ldmatrix.sync.aligned.m8n8.x4.shared.b16 {%0,%1,%2,%3}, [%4];"
                 : "=r"(r[0]), "=r"(r[1]), "=r"(r[2]), "=r"(r[3]) : "r"(addr));
}
// int8 mma: D(s32) += A(s8,16x32) * B(s8,32x8)
__device__ __forceinline__ void imma16832(int* c, const uint32_t* a, const uint32_t* b) {
    asm volatile("mma.sync.aligned.m16n8k32.row.col.s32.s8.s8.s32 "
                 "{%0,%1,%2,%3}, {%4,%5,%6,%7}, {%8,%9}, {%0,%1,%2,%3};"
                 : "+r"(c[0]), "+r"(c[1]), "+r"(c[2]), "+r"(c[3])
                 : "r"(a[0]), "r"(a[1]), "r"(a[2]), "r"(a[3]), "r"(b[0]), "r"(b[1]));
}

// (score,idx) -> lexicographically ordered u64 key (min-score, then min-idx)
__device__ __forceinline__ unsigned long long score_key(float s, int n) {
    unsigned u = __float_as_uint(s);
    u = (u & 0x80000000u) ? ~u : (u | 0x80000000u);
    return ((unsigned long long)u << 32) | (unsigned)n;
}
__device__ __forceinline__ float key_score(unsigned long long k) {
    unsigned v = (unsigned)(k >> 32);
    unsigned u = (v & 0x80000000u) ? (v & 0x7FFFFFFFu) : ~v;
    return __uint_as_float(u);
}
__device__ __forceinline__ void merge2(unsigned long long& b1, unsigned long long& b2,
                                       unsigned long long k) {
    if (k < b1) { b2 = b1; b1 = k; }
    else if (k < b2) b2 = k;
}
__device__ __forceinline__ void merge4(unsigned long long* b, unsigned long long k) {
    if (k < b[3]) {
        b[3] = k;
        if (b[3] < b[2]) { unsigned long long t = b[2]; b[2] = b[3]; b[3] = t; }
        if (b[2] < b[1]) { unsigned long long t = b[1]; b[1] = b[2]; b[2] = t; }
        if (b[1] < b[0]) { unsigned long long t = b[0]; b[0] = b[1]; b[1] = t; }
    }
}

__device__ __forceinline__ signed char q8(float x) {
    int q = __float2int_rn(x * QSCALE);
    q = q > 127 ? 127 : (q < -127 ? -127 : q);
    return (signed char)q;
}

// ---------------- normalization (+ int8 shadow copies) ----------------
__global__ void normalize_z_kernel(const float* __restrict__ z) {
    const int row = blockIdx.x, tid = threadIdx.x;
    __shared__ float sbuf[4];
    float4 v = *(const float4*)(z + (size_t)row * DDIM + tid * 4);
    float s = v.x * v.x + v.y * v.y + v.z * v.z + v.w * v.w;
    #pragma unroll
    for (int off = 16; off; off >>= 1) s += __shfl_down_sync(0xffffffffu, s, off);
    if ((tid & 31) == 0) sbuf[tid >> 5] = s;
    __syncthreads();
    float inv = 1.0f / fmaxf(sqrtf(sbuf[0] + sbuf[1] + sbuf[2] + sbuf[3]), 1e-12f);
    float4 o = {v.x * inv, v.y * inv, v.z * inv, v.w * inv};
    *(float4*)(g_zn + (size_t)row * DDIM + tid * 4) = o;
    char4 q = {q8(o.x), q8(o.y), q8(o.z), q8(o.w)};
    *(char4*)(g_a8 + (size_t)row * DDIM + tid * 4) = q;
}

__global__ void normalize_cb_kernel(const float* __restrict__ e) {
    const int row = blockIdx.x, tid = threadIdx.x;
    __shared__ float sbuf[4];
    float4 v = *(const float4*)(e + (size_t)row * DDIM + tid * 4);
    float s = v.x * v.x + v.y * v.y + v.z * v.z + v.w * v.w;
    #pragma unroll
    for (int off = 16; off; off >>= 1) s += __shfl_down_sync(0xffffffffu, s, off);
    if ((tid & 31) == 0) sbuf[tid >> 5] = s;
    __syncthreads();
    float inv = 1.0f / fmaxf(sqrtf(sbuf[0] + sbuf[1] + sbuf[2] + sbuf[3]), 1e-12f);
    float4 o = {v.x * inv, v.y * inv, v.z * inv, v.w * inv};
    *(float4*)(g_cb + (size_t)row * DDIM + tid * 4) = o;
    char4 q = {q8(o.x), q8(o.y), q8(o.z), q8(o.w)};
    *(char4*)(g_b8 + (size_t)row * DDIM + tid * 4) = q;
    float s2 = o.x * o.x + o.y * o.y + o.z * o.z + o.w * o.w;
    #pragma unroll
    for (int off = 16; off; off >>= 1) s2 += __shfl_down_sync(0xffffffffu, s2, off);
    __syncthreads();
    if ((tid & 31) == 0) sbuf[tid >> 5] = s2;
    __syncthreads();
    if (tid == 0) g_ncb[row] = sbuf[0] + sbuf[1] + sbuf[2] + sbuf[3];
}

// ---------------- phase 1: int8 IMMA GEMM + top-4 per (row, 256-wide n-tile) ----------------
// CTA 128x256, 256 threads = 8 warps (2m x 4n), warp tile 64x64, K-chunks of 128
// int8 (128B rows, SW128), 3-stage cp.async ring, s32 accumulators (exact).
#define TM 128
#define TN 256
#define NTHREADS 256
#define KCHUNK 128                       // int8 elems per chunk = 128 bytes/row
#define NCHUNKS (DDIM / KCHUNK)          // 4
#define A_BYTES (TM * 128)               // 16384
#define B_BYTES (TN * 128)               // 32768
#define STAGE_BYTES (A_BYTES + B_BYTES)  // 49152
#define NSTAGES 3
#define SNCB_OFF   (NSTAGES * STAGE_BYTES)        // 147456
#define STOP_OFF   (SNCB_OFF + TN * 4)            // 148480
#define SMEM_TOTAL (STOP_OFF + TM * 4 * 2 * 8)    // 156672

__device__ __forceinline__ void load_chunk(uint32_t sbase, int st, int c, int m0, int n0, int tid) {
    uint32_t ab = sbase + st * STAGE_BYTES;
    const signed char* asrc = g_a8 + (size_t)m0 * DDIM + c * KCHUNK;
    #pragma unroll
    for (int i = 0; i < 4; i++) {            // A: 1024 x 16B / 256 threads
        int u = tid + i * NTHREADS;
        int row = u >> 3;
        cp16(ab + SMEM_SWIZZLE_128B(row * 128 + (u & 7) * 16),
             asrc + (size_t)row * DDIM + (u & 7) * 16);
    }
    const signed char* bsrc = g_b8 + (size_t)n0 * DDIM + c * KCHUNK;
    uint32_t bb = ab + A_BYTES;
    #pragma unroll
    for (int i = 0; i < 8; i++) {            // B: 2048 x 16B
        int u = tid + i * NTHREADS;
        int row = u >> 3;
        cp16(bb + SMEM_SWIZZLE_128B(row * 128 + (u & 7) * 16),
             bsrc + (size_t)row * DDIM + (u & 7) * 16);
    }
    asm volatile("cp.async.commit_group;" ::: "memory");
}

__global__ __launch_bounds__(NTHREADS, 1) void vq_mma_kernel() {
    extern __shared__ __align__(1024) char smem[];
    const uint32_t sbase = smem_to_u32(smem);
    const int tid = threadIdx.x, wid = tid >> 5, l = tid & 31;
    const int wm = wid & 1;                  // m offset wm*64
    const int wn = wid >> 1;                 // n offset wn*64
    const int n0 = blockIdx.x * TN;
    const int m0 = blockIdx.y * TM;
    float* sncb = (float*)(smem + SNCB_OFF);
    unsigned long long (*stop)[4][2] = (unsigned long long(*)[4][2])(smem + STOP_OFF);

    sncb[tid] = g_ncb[n0 + tid];             // 256 threads, 256 vals

    int acc[4][8][4];                        // [mi 16-rows][ni 8-cols][frag] s32
    #pragma unroll
    for (int a = 0; a < 4; a++)
        #pragma unroll
        for (int b = 0; b < 8; b++)
            #pragma unroll
            for (int c = 0; c < 4; c++) acc[a][b][c] = 0;

    load_chunk(sbase, 0, 0, m0, n0, tid);
    load_chunk(sbase, 1, 1, m0, n0, tid);

    for (int c = 0; c < NCHUNKS; c++) {
        if (c + 1 < NCHUNKS) asm volatile("cp.async.wait_group 1;" ::: "memory");
        else                 asm volatile("cp.async.wait_group 0;" ::: "memory");
        __syncthreads();     // stage c ready; all warps done reading stage (c-1)
        if (c + 2 < NCHUNKS) load_chunk(sbase, (c + 2) % NSTAGES, c + 2, m0, n0, tid);

        const uint32_t a_base = sbase + (c % NSTAGES) * STAGE_BYTES;
        const uint32_t b_base = a_base + A_BYTES;
        #pragma unroll
        for (int ks = 0; ks < 4; ks++) {     // 4 x k32 (32 bytes) per chunk
            uint32_t af[4][4];
            #pragma unroll
            for (int mi = 0; mi < 4; mi++) {
                int row = wm * 64 + mi * 16 + (l & 15);
                uint32_t off = row * 128 + ks * 32 + (l >> 4) * 16;
                ldsm_x4(af[mi], a_base + SMEM_SWIZZLE_128B(off));
            }
            uint32_t bf[8][2];
            #pragma unroll
            for (int nq = 0; nq < 4; nq++) { // x4 = two n8 tiles per ldmatrix
                int row = wn * 64 + nq * 16 + (l & 7) + ((l >> 4) << 3);
                uint32_t off = row * 128 + ks * 32 + ((l >> 3) & 1) * 16;
                uint32_t r[4];
                ldsm_x4(r, b_base + SMEM_SWIZZLE_128B(off));
                bf[nq * 2][0] = r[0]; bf[nq * 2][1] = r[1];
                bf[nq * 2 + 1][0] = r[2]; bf[nq * 2 + 1][1] = r[3];
            }
            #pragma unroll
            for (int mi = 0; mi < 4; mi++)
                #pragma unroll
                for (int ni = 0; ni < 8; ni++)
                    imma16832(acc[mi][ni], af[mi], bf[ni]);
        }
    }
    __syncthreads();   // last stage fully read; smem stop region safe to use

    // ---- epilogue: per-warp top-2 per row, merged to top-4 per 256-tile ----
    // frag: c0:(r=l>>2, col=(l&3)*2) c1:(r,col+1) c2:(r+8,col) c3:(r+8,col+1)
    #pragma unroll
    for (int mi = 0; mi < 4; mi++) {
        #pragma unroll
        for (int half = 0; half < 2; half++) {
            unsigned long long b1 = ~0ull, b2 = ~0ull;
            #pragma unroll
            for (int ni = 0; ni < 8; ni++) {
                int col = wn * 64 + ni * 8 + (l & 3) * 2;
                float s0 = sncb[col]     - (float)acc[mi][ni][half * 2 + 0] * INV2SS;
                float s1 = sncb[col + 1] - (float)acc[mi][ni][half * 2 + 1] * INV2SS;
                merge2(b1, b2, score_key(s0, n0 + col));
                merge2(b1, b2, score_key(s1, n0 + col + 1));
            }
            // reduce across the 4 lanes sharing this row
            #pragma unroll
            for (int off = 1; off <= 2; off <<= 1) {
                unsigned long long o1 = __shfl_xor_sync(0xffffffffu, b1, off);
                unsigned long long o2 = __shfl_xor_sync(0xffffffffu, b2, off);
                unsigned long long hi = b1 > o1 ? b1 : o1;
                b1 = b1 < o1 ? b1 : o1;
                unsigned long long lo2 = b2 < o2 ? b2 : o2;
                b2 = hi < lo2 ? hi : lo2;
            }
            if ((l & 3) == 0) {
                int rloc = wm * 64 + mi * 16 + half * 8 + (l >> 2);
                stop[rloc][wn][0] = b1;
                stop[rloc][wn][1] = b2;
            }
        }
    }
    __syncthreads();
    if (tid < TM) {
        unsigned long long t[4] = {~0ull, ~0ull, ~0ull, ~0ull};
        #pragma unroll
        for (int w = 0; w < 4; w++) {
            merge4(t, stop[tid][w][0]);
            merge4(t, stop[tid][w][1]);
        }
        size_t o = (size_t)(m0 + tid) * 128 + blockIdx.x * 4;
        g_part[o] = t[0]; g_part[o + 1] = t[1];
        g_part[o + 2] = t[2]; g_part[o + 3] = t[3];
    }
}

// ---------------- phase 2: exact fp32 rescore (ballot-filtered) ----------------
__global__ void select_kernel() {
    const int lane = threadIdx.x & 31;
    const int row = (blockIdx.x * blockDim.x + threadIdx.x) >> 5;
    const unsigned long long* cand = g_part + (size_t)row * 128;

    unsigned long long k[4];
    #pragma unroll
    for (int i = 0; i < 4; i++) k[i] = cand[lane * 4 + i];
    unsigned long long mn = k[0];
    #pragma unroll
    for (int i = 1; i < 4; i++) if (k[i] < mn) mn = k[i];
    #pragma unroll
    for (int off = 16; off; off >>= 1) {
        unsigned long long o = __shfl_xor_sync(0xffffffffu, mn, off);
        if (o < mn) mn = o;
    }
    const float lim = key_score(mn) + 2e-2f;   // tau >> max int8 score noise (~1.1e-2)

    unsigned bal[4];
    #pragma unroll
    for (int i = 0; i < 4; i++)
        bal[i] = __ballot_sync(0xffffffffu, key_score(k[i]) <= lim);

    float4 zv[4];
    const float4* zr = (const float4*)(g_zn + (size_t)row * DDIM);
    #pragma unroll
    for (int t = 0; t < 4; t++) zv[t] = zr[lane * 4 + t];

    unsigned long long best = ~0ull;
    #pragma unroll 1
    for (int which = 0; which < 4; which++) {
        unsigned b = bal[which];
        while (b) {
            int src = __ffs(b) - 1;
            b &= b - 1;
            unsigned long long kk = __shfl_sync(0xffffffffu, k[which], src);
            const int idx = (int)(kk & 0xFFFFFFFFull);
            const float4* cr = (const float4*)(g_cb + (size_t)idx * DDIM);
            float p = 0.0f;
            #pragma unroll
            for (int t = 0; t < 4; t++) {
                float4 cv = cr[lane * 4 + t];
                p += zv[t].x * cv.x + zv[t].y * cv.y + zv[t].z * cv.z + zv[t].w * cv.w;
            }
            #pragma unroll
            for (int off = 16; off; off >>= 1) p += __shfl_xor_sync(0xffffffffu, p, off);
            unsigned long long ek = score_key(g_ncb[idx] - 2.0f * p, idx);
            if (ek < best) best = ek;
        }
    }
    if (lane == 0) g_bestidx[row] = (int)(best & 0xFFFFFFFFull);
}

// ---------------- gather + projection + index output ----------------
__global__ void proj_kernel(float* __restrict__ out, int out_size) {
    const int row = blockIdx.x;
    const int tid = threadIdx.x;   // 128
    __shared__ float sbuf[4];

    const int idx = g_bestidx[row];
    const float4 zv = *(const float4*)(g_zn + (size_t)row * DDIM + tid * 4);
    const float4 cv = *(const float4*)(g_cb + (size_t)idx * DDIM + tid * 4);
    float p = zv.x * cv.x + zv.y * cv.y + zv.z * cv.z + zv.w * cv.w;
    #pragma unroll
    for (int off = 16; off; off >>= 1) p += __shfl_down_sync(0xffffffffu, p, off);
    if ((tid & 31) == 0) sbuf[tid >> 5] = p;
    __syncthreads();
    const float dot = sbuf[0] + sbuf[1] + sbuf[2] + sbuf[3];

    float4 o = {dot * cv.x, dot * cv.y, dot * cv.z, dot * cv.w};
    *(float4*)(out + (size_t)row * DDIM + tid * 4) = o;

    if (tid == 0 && out_size >= NROWS * DDIM + NROWS)
        out[(size_t)NROWS * DDIM + row] = (float)idx;
}

extern "C" void kernel_launch(void* const* d_in, const int* in_sizes, int n_in,
                              void* d_out, int out_size) {
    const float* z   = (const float*)d_in[0];
    const float* emb = (const float*)d_in[1];
    if (n_in >= 2 && in_sizes[0] == KCODES * DDIM && in_sizes[1] == NROWS * DDIM) {
        const float* t = z; z = emb; emb = t;
    }

    cudaFuncSetAttribute(vq_mma_kernel, cudaFuncAttributeMaxDynamicSharedMemorySize, SMEM_TOTAL);

    normalize_z_kernel<<<NROWS, 128>>>(z);
    normalize_cb_kernel<<<KCODES, 128>>>(emb);

    dim3 grid(KCODES / TN, NROWS / TM);   // (32, 512)
    vq_mma_kernel<<<grid, NTHREADS, SMEM_TOTAL>>>();

    select_kernel<<<NROWS / 8, 256>>>();
    proj_kernel<<<NROWS, 128>>>((float*)d_out, out_size);
}

// round 14
// speedup vs baseline: 2.1587x; 2.1587x over previous
#include <cuda_runtime.h>
#include <cuda_fp16.h>
#include <cstdint>

#define NROWS 65536
#define KCODES 8192
#define DDIM 512

// ---------------- static device scratch ----------------
__device__ float  g_zn[(size_t)NROWS * DDIM];     // normalized z (fp32)
__device__ float  g_cb[(size_t)KCODES * DDIM];    // normalized codebook (fp32)
__device__ float  g_ncb[KCODES];                  // ||cb||^2 (of rounded normalized row)
__device__ __half g_ah[(size_t)NROWS * DDIM];     // fp16(zn)
__device__ __half g_bh[(size_t)KCODES * DDIM];    // fp16(cb)
__device__ unsigned long long g_part[(size_t)NROWS * 128]; // top4 per (row, 256-wide ntile)
__device__ int    g_bestidx[NROWS];

// ---------------- helpers ----------------
__device__ __forceinline__ uint32_t smem_to_u32(const void* p) {
    uint32_t a;
    asm("{ .reg .u64 t; cvta.to.shared.u64 t, %1; cvt.u32.u64 %0, t; }" : "=r"(a) : "l"(p));
    return a;
}
#define SMEM_SWIZZLE_128B(o) ((o) ^ (((o) >> 3) & 0x70))

__device__ __forceinline__ void cp16(uint32_t dst, const void* src) {
    asm volatile("cp.async.cg.shared.global [%0], [%1], 16;" :: "r"(dst), "l"(src));
}
__device__ __forceinline__ void ldsm_x4(uint32_t* r, uint32_t addr) {
    asm volatile("ldmatrix.sync.aligned.m8n8.x4.shared.b16 {%0,%1,%2,%3}, [%4];"
                 : "=r"(r[0]), "=r"(r[1]), "=r"(r[2]), "=r"(r[3]) : "r"(addr));
}
// f16-accumulate HMMA: D(f16x2 x2) += A(f16 16x16) * B(f16 16x8)
__device__ __forceinline__ void mma16816_f16acc(uint32_t* c, const uint32_t* a,
                                                const uint32_t* b) {
    asm volatile("mma.sync.aligned.m16n8k16.row.col.f16.f16.f16.f16 "
                 "{%0,%1}, {%2,%3,%4,%5}, {%6,%7}, {%0,%1};"
                 : "+r"(c[0]), "+r"(c[1])
                 : "r"(a[0]), "r"(a[1]), "r"(a[2]), "r"(a[3]), "r"(b[0]), "r"(b[1]));
}

// (score,idx) -> lexicographically ordered u64 key (min-score, then min-idx)
__device__ __forceinline__ unsigned long long score_key(float s, int n) {
    unsigned u = __float_as_uint(s);
    u = (u & 0x80000000u) ? ~u : (u | 0x80000000u);
    return ((unsigned long long)u << 32) | (unsigned)n;
}
__device__ __forceinline__ float key_score(unsigned long long k) {
    unsigned v = (unsigned)(k >> 32);
    unsigned u = (v & 0x80000000u) ? (v & 0x7FFFFFFFu) : ~v;
    return __uint_as_float(u);
}
__device__ __forceinline__ void merge2(unsigned long long& b1, unsigned long long& b2,
                                       unsigned long long k) {
    if (k < b1) { b2 = b1; b1 = k; }
    else if (k < b2) b2 = k;
}
__device__ __forceinline__ void merge4(unsigned long long* b, unsigned long long k) {
    if (k < b[3]) {
        b[3] = k;
        if (b[3] < b[2]) { unsigned long long t = b[2]; b[2] = b[3]; b[3] = t; }
        if (b[2] < b[1]) { unsigned long long t = b[1]; b[1] = b[2]; b[2] = t; }
        if (b[1] < b[0]) { unsigned long long t = b[0]; b[0] = b[1]; b[1] = t; }
    }
}

// ---------------- normalization (+ fp16 shadow copies) ----------------
__global__ void normalize_z_kernel(const float* __restrict__ z) {
    const int row = blockIdx.x, tid = threadIdx.x;
    __shared__ float sbuf[4];
    float4 v = *(const float4*)(z + (size_t)row * DDIM + tid * 4);
    float s = v.x * v.x + v.y * v.y + v.z * v.z + v.w * v.w;
    #pragma unroll
    for (int off = 16; off; off >>= 1) s += __shfl_down_sync(0xffffffffu, s, off);
    if ((tid & 31) == 0) sbuf[tid >> 5] = s;
    __syncthreads();
    float inv = 1.0f / fmaxf(sqrtf(sbuf[0] + sbuf[1] + sbuf[2] + sbuf[3]), 1e-12f);
    float4 o = {v.x * inv, v.y * inv, v.z * inv, v.w * inv};
    *(float4*)(g_zn + (size_t)row * DDIM + tid * 4) = o;
    __half2* hp = (__half2*)(g_ah + (size_t)row * DDIM + tid * 4);
    hp[0] = __floats2half2_rn(o.x, o.y);
    hp[1] = __floats2half2_rn(o.z, o.w);
}

__global__ void normalize_cb_kernel(const float* __restrict__ e) {
    const int row = blockIdx.x, tid = threadIdx.x;
    __shared__ float sbuf[4];
    float4 v = *(const float4*)(e + (size_t)row * DDIM + tid * 4);
    float s = v.x * v.x + v.y * v.y + v.z * v.z + v.w * v.w;
    #pragma unroll
    for (int off = 16; off; off >>= 1) s += __shfl_down_sync(0xffffffffu, s, off);
    if ((tid & 31) == 0) sbuf[tid >> 5] = s;
    __syncthreads();
    float inv = 1.0f / fmaxf(sqrtf(sbuf[0] + sbuf[1] + sbuf[2] + sbuf[3]), 1e-12f);
    float4 o = {v.x * inv, v.y * inv, v.z * inv, v.w * inv};
    *(float4*)(g_cb + (size_t)row * DDIM + tid * 4) = o;
    __half2* hp = (__half2*)(g_bh + (size_t)row * DDIM + tid * 4);
    hp[0] = __floats2half2_rn(o.x, o.y);
    hp[1] = __floats2half2_rn(o.z, o.w);
    float s2 = o.x * o.x + o.y * o.y + o.z * o.z + o.w * o.w;
    #pragma unroll
    for (int off = 16; off; off >>= 1) s2 += __shfl_down_sync(0xffffffffu, s2, off);
    __syncthreads();
    if ((tid & 31) == 0) sbuf[tid >> 5] = s2;
    __syncthreads();
    if (tid == 0) g_ncb[row] = sbuf[0] + sbuf[1] + sbuf[2] + sbuf[3];
}

// ---------------- phase 1: fp16 HMMA (fp16 accum) + top-4 per (row, 256-wide n-tile) ----------------
// CTA 128x256, 8 warps (2m x 4n), warp tile 64x64, K-chunks of 64 fp16 (128B rows,
// SW128), 3-stage cp.async ring, fp16x2 accumulators.
#define TM 128
#define TN 256
#define NTHREADS 256
#define KCHUNK 64
#define NCHUNKS (DDIM / KCHUNK)          // 8
#define A_BYTES (TM * 128)               // 16384
#define B_BYTES (TN * 128)               // 32768
#define STAGE_BYTES (A_BYTES + B_BYTES)  // 49152
#define NSTAGES 3
#define SNCB_OFF   (NSTAGES * STAGE_BYTES)        // 147456
#define STOP_OFF   (SNCB_OFF + TN * 4)            // 148480
#define SMEM_TOTAL (STOP_OFF + TM * 4 * 2 * 8)    // 156672

__device__ __forceinline__ void load_chunk(uint32_t sbase, int st, int c, int m0, int n0, int tid) {
    uint32_t ab = sbase + st * STAGE_BYTES;
    const __half* asrc = g_ah + (size_t)m0 * DDIM + c * KCHUNK;
    #pragma unroll
    for (int i = 0; i < 4; i++) {            // A: 1024 x 16B / 256 threads
        int u = tid + i * NTHREADS;
        int row = u >> 3;
        cp16(ab + SMEM_SWIZZLE_128B(row * 128 + (u & 7) * 16),
             asrc + (size_t)row * DDIM + (u & 7) * 8);
    }
    const __half* bsrc = g_bh + (size_t)n0 * DDIM + c * KCHUNK;
    uint32_t bb = ab + A_BYTES;
    #pragma unroll
    for (int i = 0; i < 8; i++) {            // B: 2048 x 16B
        int u = tid + i * NTHREADS;
        int row = u >> 3;
        cp16(bb + SMEM_SWIZZLE_128B(row * 128 + (u & 7) * 16),
             bsrc + (size_t)row * DDIM + (u & 7) * 8);
    }
    asm volatile("cp.async.commit_group;" ::: "memory");
}

__global__ __launch_bounds__(NTHREADS, 1) void vq_mma_kernel() {
    extern __shared__ __align__(1024) char smem[];
    const uint32_t sbase = smem_to_u32(smem);
    const int tid = threadIdx.x, wid = tid >> 5, l = tid & 31;
    const int wm = wid & 1;                  // m offset wm*64
    const int wn = wid >> 1;                 // n offset wn*64
    const int n0 = blockIdx.x * TN;
    const int m0 = blockIdx.y * TM;
    float* sncb = (float*)(smem + SNCB_OFF);
    unsigned long long (*stop)[4][2] = (unsigned long long(*)[4][2])(smem + STOP_OFF);

    sncb[tid] = g_ncb[n0 + tid];             // 256 threads, 256 vals

    uint32_t acc[4][8][2];                   // [mi 16-rows][ni 8-cols][f16x2 frag]
    #pragma unroll
    for (int a = 0; a < 4; a++)
        #pragma unroll
        for (int b = 0; b < 8; b++) { acc[a][b][0] = 0u; acc[a][b][1] = 0u; }

    load_chunk(sbase, 0, 0, m0, n0, tid);
    load_chunk(sbase, 1, 1, m0, n0, tid);

    for (int c = 0; c < NCHUNKS; c++) {
        if (c + 1 < NCHUNKS) asm volatile("cp.async.wait_group 1;" ::: "memory");
        else                 asm volatile("cp.async.wait_group 0;" ::: "memory");
        __syncthreads();     // stage c ready; all warps done reading stage (c-1)
        if (c + 2 < NCHUNKS) load_chunk(sbase, (c + 2) % NSTAGES, c + 2, m0, n0, tid);

        const uint32_t a_base = sbase + (c % NSTAGES) * STAGE_BYTES;
        const uint32_t b_base = a_base + A_BYTES;
        #pragma unroll
        for (int ks = 0; ks < 4; ks++) {     // 4 x k16 per chunk
            uint32_t af[4][4];
            #pragma unroll
            for (int mi = 0; mi < 4; mi++) {
                int row = wm * 64 + mi * 16 + (l & 15);
                uint32_t off = row * 128 + ks * 32 + (l >> 4) * 16;
                ldsm_x4(af[mi], a_base + SMEM_SWIZZLE_128B(off));
            }
            uint32_t bf[8][2];
            #pragma unroll
            for (int nq = 0; nq < 4; nq++) { // x4 = two n8 tiles per ldmatrix
                int row = wn * 64 + nq * 16 + (l & 7) + ((l >> 4) << 3);
                uint32_t off = row * 128 + ks * 32 + ((l >> 3) & 1) * 16;
                uint32_t r[4];
                ldsm_x4(r, b_base + SMEM_SWIZZLE_128B(off));
                bf[nq * 2][0] = r[0]; bf[nq * 2][1] = r[1];
                bf[nq * 2 + 1][0] = r[2]; bf[nq * 2 + 1][1] = r[3];
            }
            #pragma unroll
            for (int mi = 0; mi < 4; mi++)
                #pragma unroll
                for (int ni = 0; ni < 8; ni++)
                    mma16816_f16acc(acc[mi][ni], af[mi], bf[ni]);
        }
    }
    __syncthreads();   // last stage fully read; smem stop region safe to use

    // ---- epilogue: per-warp top-2 per row, merged to top-4 per 256-tile ----
    // f16-acc frag: c[0] = halves {(r=l>>2, col=(l&3)*2), (r, col+1)}
    //               c[1] = halves {(r+8, col), (r+8, col+1)}
    #pragma unroll
    for (int mi = 0; mi < 4; mi++) {
        #pragma unroll
        for (int half = 0; half < 2; half++) {
            unsigned long long b1 = ~0ull, b2 = ~0ull;
            #pragma unroll
            for (int ni = 0; ni < 8; ni++) {
                int col = wn * 64 + ni * 8 + (l & 3) * 2;
                float2 d = __half22float2(*(__half2*)&acc[mi][ni][half]);
                float s0 = sncb[col]     - 2.0f * d.x;
                float s1 = sncb[col + 1] - 2.0f * d.y;
                merge2(b1, b2, score_key(s0, n0 + col));
                merge2(b1, b2, score_key(s1, n0 + col + 1));
            }
            // reduce across the 4 lanes sharing this row
            #pragma unroll
            for (int off = 1; off <= 2; off <<= 1) {
                unsigned long long o1 = __shfl_xor_sync(0xffffffffu, b1, off);
                unsigned long long o2 = __shfl_xor_sync(0xffffffffu, b2, off);
                unsigned long long hi = b1 > o1 ? b1 : o1;
                b1 = b1 < o1 ? b1 : o1;
                unsigned long long lo2 = b2 < o2 ? b2 : o2;
                b2 = hi < lo2 ? hi : lo2;
            }
            if ((l & 3) == 0) {
                int rloc = wm * 64 + mi * 16 + half * 8 + (l >> 2);
                stop[rloc][wn][0] = b1;
                stop[rloc][wn][1] = b2;
            }
        }
    }
    __syncthreads();
    if (tid < TM) {
        unsigned long long t[4] = {~0ull, ~0ull, ~0ull, ~0ull};
        #pragma unroll
        for (int w = 0; w < 4; w++) {
            merge4(t, stop[tid][w][0]);
            merge4(t, stop[tid][w][1]);
        }
        size_t o = (size_t)(m0 + tid) * 128 + blockIdx.x * 4;
        g_part[o] = t[0]; g_part[o + 1] = t[1];
        g_part[o + 2] = t[2]; g_part[o + 3] = t[3];
    }
}

// ---------------- phase 2: exact fp32 rescore (ballot-filtered) ----------------
__global__ void select_kernel() {
    const int lane = threadIdx.x & 31;
    const int row = (blockIdx.x * blockDim.x + threadIdx.x) >> 5;
    const unsigned long long* cand = g_part + (size_t)row * 128;

    unsigned long long k[4];
    #pragma unroll
    for (int i = 0; i < 4; i++) k[i] = cand[lane * 4 + i];
    unsigned long long mn = k[0];
    #pragma unroll
    for (int i = 1; i < 4; i++) if (k[i] < mn) mn = k[i];
    #pragma unroll
    for (int off = 16; off; off >>= 1) {
        unsigned long long o = __shfl_xor_sync(0xffffffffu, mn, off);
        if (o < mn) mn = o;
    }
    const float lim = key_score(mn) + 1e-2f;   // tau >> fp16-accum score noise (~1.4e-3 RMS)

    unsigned bal[4];
    #pragma unroll
    for (int i = 0; i < 4; i++)
        bal[i] = __ballot_sync(0xffffffffu, key_score(k[i]) <= lim);

    float4 zv[4];
    const float4* zr = (const float4*)(g_zn + (size_t)row * DDIM);
    #pragma unroll
    for (int t = 0; t < 4; t++) zv[t] = zr[lane * 4 + t];

    unsigned long long best = ~0ull;
    #pragma unroll 1
    for (int which = 0; which < 4; which++) {
        unsigned b = bal[which];
        while (b) {
            int src = __ffs(b) - 1;
            b &= b - 1;
            unsigned long long kk = __shfl_sync(0xffffffffu, k[which], src);
            const int idx = (int)(kk & 0xFFFFFFFFull);
            const float4* cr = (const float4*)(g_cb + (size_t)idx * DDIM);
            float p = 0.0f;
            #pragma unroll
            for (int t = 0; t < 4; t++) {
                float4 cv = cr[lane * 4 + t];
                p += zv[t].x * cv.x + zv[t].y * cv.y + zv[t].z * cv.z + zv[t].w * cv.w;
            }
            #pragma unroll
            for (int off = 16; off; off >>= 1) p += __shfl_xor_sync(0xffffffffu, p, off);
            unsigned long long ek = score_key(g_ncb[idx] - 2.0f * p, idx);
            if (ek < best) best = ek;
        }
    }
    if (lane == 0) g_bestidx[row] = (int)(best & 0xFFFFFFFFull);
}

// ---------------- gather + projection + index output ----------------
__global__ void proj_kernel(float* __restrict__ out, int out_size) {
    const int row = blockIdx.x;
    const int tid = threadIdx.x;   // 128
    __shared__ float sbuf[4];

    const int idx = g_bestidx[row];
    const float4 zv = *(const float4*)(g_zn + (size_t)row * DDIM + tid * 4);
    const float4 cv = *(const float4*)(g_cb + (size_t)idx * DDIM + tid * 4);
    float p = zv.x * cv.x + zv.y * cv.y + zv.z * cv.z + zv.w * cv.w;
    #pragma unroll
    for (int off = 16; off; off >>= 1) p += __shfl_down_sync(0xffffffffu, p, off);
    if ((tid & 31) == 0) sbuf[tid >> 5] = p;
    __syncthreads();
    const float dot = sbuf[0] + sbuf[1] + sbuf[2] + sbuf[3];

    float4 o = {dot * cv.x, dot * cv.y, dot * cv.z, dot * cv.w};
    *(float4*)(out + (size_t)row * DDIM + tid * 4) = o;

    if (tid == 0 && out_size >= NROWS * DDIM + NROWS)
        out[(size_t)NROWS * DDIM + row] = (float)idx;
}

extern "C" void kernel_launch(void* const* d_in, const int* in_sizes, int n_in,
                              void* d_out, int out_size) {
    const float* z   = (const float*)d_in[0];
    const float* emb = (const float*)d_in[1];
    if (n_in >= 2 && in_sizes[0] == KCODES * DDIM && in_sizes[1] == NROWS * DDIM) {
        const float* t = z; z = emb; emb = t;
    }

    cudaFuncSetAttribute(vq_mma_kernel, cudaFuncAttributeMaxDynamicSharedMemorySize, SMEM_TOTAL);

    normalize_z_kernel<<<NROWS, 128>>>(z);
    normalize_cb_kernel<<<KCODES, 128>>>(emb);

    dim3 grid(KCODES / TN, NROWS / TM);   // (32, 512)
    vq_mma_kernel<<<grid, NTHREADS, SMEM_TOTAL>>>();

    select_kernel<<<NROWS / 8, 256>>>();
    proj_kernel<<<NROWS, 128>>>((float*)d_out, out_size);
}

// round 15
// speedup vs baseline: 2.3360x; 1.0821x over previous
#include <cuda_runtime.h>
#include <cuda_fp16.h>
#include <cstdint>

#define NROWS 65536
#define KCODES 8192
#define DDIM 512

// ---------------- static device scratch ----------------
__device__ float  g_cb[(size_t)KCODES * DDIM];    // normalized codebook (fp32)
__device__ float  g_ncb[KCODES];                  // ||cb||^2 (of rounded normalized row)
__device__ float  g_invn[NROWS];                  // 1/max(||z_row||, eps)
__device__ __half g_ah[(size_t)NROWS * DDIM];     // fp16(zn)
__device__ __half g_bh[(size_t)KCODES * DDIM];    // fp16(cb)
__device__ unsigned long long g_part[(size_t)NROWS * 64]; // top2 per (row, 256-wide ntile)

// ---------------- helpers ----------------
__device__ __forceinline__ uint32_t smem_to_u32(const void* p) {
    uint32_t a;
    asm("{ .reg .u64 t; cvta.to.shared.u64 t, %1; cvt.u32.u64 %0, t; }" : "=r"(a) : "l"(p));
    return a;
}
#define SMEM_SWIZZLE_128B(o) ((o) ^ (((o) >> 3) & 0x70))

__device__ __forceinline__ void cp16(uint32_t dst, const void* src) {
    asm volatile("cp.async.cg.shared.global [%0], [%1], 16;" :: "r"(dst), "l"(src));
}
__device__ __forceinline__ void ldsm_x4(uint32_t* r, uint32_t addr) {
    asm volatile("ldmatrix.sync.aligned.m8n8.x4.shared.b16 {%0,%1,%2,%3}, [%4];"
                 : "=r"(r[0]), "=r"(r[1]), "=r"(r[2]), "=r"(r[3]) : "r"(addr));
}
__device__ __forceinline__ void mma16816(float* c, const uint32_t* a, const uint32_t* b) {
    asm volatile("mma.sync.aligned.m16n8k16.row.col.f32.f16.f16.f32 "
                 "{%0,%1,%2,%3}, {%4,%5,%6,%7}, {%8,%9}, {%0,%1,%2,%3};"
                 : "+f"(c[0]), "+f"(c[1]), "+f"(c[2]), "+f"(c[3])
                 : "r"(a[0]), "r"(a[1]), "r"(a[2]), "r"(a[3]), "r"(b[0]), "r"(b[1]));
}

// (score,idx) -> lexicographically ordered u64 key (min-score, then min-idx)
__device__ __forceinline__ unsigned long long score_key(float s, int n) {
    unsigned u = __float_as_uint(s);
    u = (u & 0x80000000u) ? ~u : (u | 0x80000000u);
    return ((unsigned long long)u << 32) | (unsigned)n;
}
__device__ __forceinline__ float key_score(unsigned long long k) {
    unsigned v = (unsigned)(k >> 32);
    unsigned u = (v & 0x80000000u) ? (v & 0x7FFFFFFFu) : ~v;
    return __uint_as_float(u);
}
__device__ __forceinline__ void merge2(unsigned long long& b1, unsigned long long& b2,
                                       unsigned long long k) {
    if (k < b1) { b2 = b1; b1 = k; }
    else if (k < b2) b2 = k;
}

// ---------------- normalization (+ fp16 shadow copies) ----------------
__global__ void normalize_z_kernel(const float* __restrict__ z) {
    const int row = blockIdx.x, tid = threadIdx.x;
    __shared__ float sbuf[4];
    float4 v = *(const float4*)(z + (size_t)row * DDIM + tid * 4);
    float s = v.x * v.x + v.y * v.y + v.z * v.z + v.w * v.w;
    #pragma unroll
    for (int off = 16; off; off >>= 1) s += __shfl_down_sync(0xffffffffu, s, off);
    if ((tid & 31) == 0) sbuf[tid >> 5] = s;
    __syncthreads();
    float inv = 1.0f / fmaxf(sqrtf(sbuf[0] + sbuf[1] + sbuf[2] + sbuf[3]), 1e-12f);
    float4 o = {v.x * inv, v.y * inv, v.z * inv, v.w * inv};
    __half2* hp = (__half2*)(g_ah + (size_t)row * DDIM + tid * 4);
    hp[0] = __floats2half2_rn(o.x, o.y);
    hp[1] = __floats2half2_rn(o.z, o.w);
    if (tid == 0) g_invn[row] = inv;
}

__global__ void normalize_cb_kernel(const float* __restrict__ e) {
    const int row = blockIdx.x, tid = threadIdx.x;
    __shared__ float sbuf[4];
    float4 v = *(const float4*)(e + (size_t)row * DDIM + tid * 4);
    float s = v.x * v.x + v.y * v.y + v.z * v.z + v.w * v.w;
    #pragma unroll
    for (int off = 16; off; off >>= 1) s += __shfl_down_sync(0xffffffffu, s, off);
    if ((tid & 31) == 0) sbuf[tid >> 5] = s;
    __syncthreads();
    float inv = 1.0f / fmaxf(sqrtf(sbuf[0] + sbuf[1] + sbuf[2] + sbuf[3]), 1e-12f);
    float4 o = {v.x * inv, v.y * inv, v.z * inv, v.w * inv};
    *(float4*)(g_cb + (size_t)row * DDIM + tid * 4) = o;
    __half2* hp = (__half2*)(g_bh + (size_t)row * DDIM + tid * 4);
    hp[0] = __floats2half2_rn(o.x, o.y);
    hp[1] = __floats2half2_rn(o.z, o.w);
    float s2 = o.x * o.x + o.y * o.y + o.z * o.z + o.w * o.w;
    #pragma unroll
    for (int off = 16; off; off >>= 1) s2 += __shfl_down_sync(0xffffffffu, s2, off);
    __syncthreads();
    if ((tid & 31) == 0) sbuf[tid >> 5] = s2;
    __syncthreads();
    if (tid == 0) g_ncb[row] = sbuf[0] + sbuf[1] + sbuf[2] + sbuf[3];
}

// ---------------- phase 1: fp16 HMMA GEMM + top-2 per (row, 256-wide n-tile) ----------------
// CTA 128x256, 8 warps (2m x 4n), warp tile 64x64, K-chunks of 64 fp16 (128B rows,
// SW128), 3-stage cp.async ring, fp32 accumulators. (R10 configuration — best known.)
#define TM 128
#define TN 256
#define NTHREADS 256
#define KCHUNK 64
#define NCHUNKS (DDIM / KCHUNK)          // 8
#define A_BYTES (TM * 128)               // 16384
#define B_BYTES (TN * 128)               // 32768
#define STAGE_BYTES (A_BYTES + B_BYTES)  // 49152
#define NSTAGES 3
#define SNCB_OFF   (NSTAGES * STAGE_BYTES)        // 147456
#define STOP_OFF   (SNCB_OFF + TN * 4)            // 148480
#define SMEM_TOTAL (STOP_OFF + TM * 4 * 2 * 8)    // 156672

__device__ __forceinline__ void load_chunk(uint32_t sbase, int st, int c, int m0, int n0, int tid) {
    uint32_t ab = sbase + st * STAGE_BYTES;
    const __half* asrc = g_ah + (size_t)m0 * DDIM + c * KCHUNK;
    #pragma unroll
    for (int i = 0; i < 4; i++) {            // A: 1024 x 16B / 256 threads
        int u = tid + i * NTHREADS;
        int row = u >> 3;
        cp16(ab + SMEM_SWIZZLE_128B(row * 128 + (u & 7) * 16),
             asrc + (size_t)row * DDIM + (u & 7) * 8);
    }
    const __half* bsrc = g_bh + (size_t)n0 * DDIM + c * KCHUNK;
    uint32_t bb = ab + A_BYTES;
    #pragma unroll
    for (int i = 0; i < 8; i++) {            // B: 2048 x 16B
        int u = tid + i * NTHREADS;
        int row = u >> 3;
        cp16(bb + SMEM_SWIZZLE_128B(row * 128 + (u & 7) * 16),
             bsrc + (size_t)row * DDIM + (u & 7) * 8);
    }
    asm volatile("cp.async.commit_group;" ::: "memory");
}

__global__ __launch_bounds__(NTHREADS, 1) void vq_mma_kernel() {
    extern __shared__ __align__(1024) char smem[];
    const uint32_t sbase = smem_to_u32(smem);
    const int tid = threadIdx.x, wid = tid >> 5, l = tid & 31;
    const int wm = wid & 1;                  // m offset wm*64
    const int wn = wid >> 1;                 // n offset wn*64
    const int n0 = blockIdx.x * TN;
    const int m0 = blockIdx.y * TM;
    float* sncb = (float*)(smem + SNCB_OFF);
    unsigned long long (*stop)[4][2] = (unsigned long long(*)[4][2])(smem + STOP_OFF);

    sncb[tid] = g_ncb[n0 + tid];             // 256 threads, 256 vals

    float acc[4][8][4];                      // [mi 16-rows][ni 8-cols][frag]
    #pragma unroll
    for (int a = 0; a < 4; a++)
        #pragma unroll
        for (int b = 0; b < 8; b++)
            #pragma unroll
            for (int c = 0; c < 4; c++) acc[a][b][c] = 0.0f;

    load_chunk(sbase, 0, 0, m0, n0, tid);
    load_chunk(sbase, 1, 1, m0, n0, tid);

    for (int c = 0; c < NCHUNKS; c++) {
        if (c + 1 < NCHUNKS) asm volatile("cp.async.wait_group 1;" ::: "memory");
        else                 asm volatile("cp.async.wait_group 0;" ::: "memory");
        __syncthreads();     // stage c ready; all warps done reading stage (c-1)
        if (c + 2 < NCHUNKS) load_chunk(sbase, (c + 2) % NSTAGES, c + 2, m0, n0, tid);

        const uint32_t a_base = sbase + (c % NSTAGES) * STAGE_BYTES;
        const uint32_t b_base = a_base + A_BYTES;
        #pragma unroll
        for (int ks = 0; ks < 4; ks++) {     // 4 x k16 per chunk
            uint32_t af[4][4];
            #pragma unroll
            for (int mi = 0; mi < 4; mi++) {
                int row = wm * 64 + mi * 16 + (l & 15);
                uint32_t off = row * 128 + ks * 32 + (l >> 4) * 16;
                ldsm_x4(af[mi], a_base + SMEM_SWIZZLE_128B(off));
            }
            uint32_t bf[8][2];
            #pragma unroll
            for (int nq = 0; nq < 4; nq++) { // x4 = two n8 tiles per ldmatrix
                int row = wn * 64 + nq * 16 + (l & 7) + ((l >> 4) << 3);
                uint32_t off = row * 128 + ks * 32 + ((l >> 3) & 1) * 16;
                uint32_t r[4];
                ldsm_x4(r, b_base + SMEM_SWIZZLE_128B(off));
                bf[nq * 2][0] = r[0]; bf[nq * 2][1] = r[1];
                bf[nq * 2 + 1][0] = r[2]; bf[nq * 2 + 1][1] = r[3];
            }
            #pragma unroll
            for (int mi = 0; mi < 4; mi++)
                #pragma unroll
                for (int ni = 0; ni < 8; ni++)
                    mma16816(acc[mi][ni], af[mi], bf[ni]);
        }
    }
    __syncthreads();   // last stage fully read; smem stop region safe to use

    // ---- epilogue: per-row top-2 across this CTA's 256 codes ----
    // frag: c0:(r=l>>2, col=(l&3)*2) c1:(r,col+1) c2:(r+8,col) c3:(r+8,col+1)
    #pragma unroll
    for (int mi = 0; mi < 4; mi++) {
        #pragma unroll
        for (int half = 0; half < 2; half++) {
            unsigned long long b1 = ~0ull, b2 = ~0ull;
            #pragma unroll
            for (int ni = 0; ni < 8; ni++) {
                int col = wn * 64 + ni * 8 + (l & 3) * 2;
                float s0 = sncb[col]     - 2.0f * acc[mi][ni][half * 2 + 0];
                float s1 = sncb[col + 1] - 2.0f * acc[mi][ni][half * 2 + 1];
                merge2(b1, b2, score_key(s0, n0 + col));
                merge2(b1, b2, score_key(s1, n0 + col + 1));
            }
            // reduce across the 4 lanes sharing this row
            #pragma unroll
            for (int off = 1; off <= 2; off <<= 1) {
                unsigned long long o1 = __shfl_xor_sync(0xffffffffu, b1, off);
                unsigned long long o2 = __shfl_xor_sync(0xffffffffu, b2, off);
                unsigned long long hi = b1 > o1 ? b1 : o1;
                b1 = b1 < o1 ? b1 : o1;
                unsigned long long lo2 = b2 < o2 ? b2 : o2;
                b2 = hi < lo2 ? hi : lo2;
            }
            if ((l & 3) == 0) {
                int rloc = wm * 64 + mi * 16 + half * 8 + (l >> 2);
                stop[rloc][wn][0] = b1;
                stop[rloc][wn][1] = b2;
            }
        }
    }
    __syncthreads();
    if (tid < TM) {
        unsigned long long t1 = ~0ull, t2 = ~0ull;
        #pragma unroll
        for (int w = 0; w < 4; w++) {
            merge2(t1, t2, stop[tid][w][0]);
            merge2(t1, t2, stop[tid][w][1]);
        }
        size_t o = (size_t)(m0 + tid) * 64 + blockIdx.x * 2;
        g_part[o] = t1;
        g_part[o + 1] = t2;
    }
}

// ---------------- phase 2: exact fp32 rescore + projection + index (fused) ----------------
__global__ void select_proj_kernel(const float* __restrict__ z, float* __restrict__ out,
                                   int out_size) {
    const int lane = threadIdx.x & 31;
    const int row = (blockIdx.x * blockDim.x + threadIdx.x) >> 5;
    const unsigned long long* cand = g_part + (size_t)row * 64;

    unsigned long long k0 = cand[lane * 2], k1 = cand[lane * 2 + 1];
    unsigned long long mn = k0 < k1 ? k0 : k1;
    #pragma unroll
    for (int off = 16; off; off >>= 1) {
        unsigned long long o = __shfl_xor_sync(0xffffffffu, mn, off);
        if (o < mn) mn = o;
    }
    const float lim = key_score(mn) + 4e-3f;   // tau >> max fp16 score error (~8e-4)

    unsigned bal0 = __ballot_sync(0xffffffffu, key_score(k0) <= lim);
    unsigned bal1 = __ballot_sync(0xffffffffu, key_score(k1) <= lim);

    // zn values recomputed exactly: fl(z_i * inv) == stored zn of prior versions
    const float inv = g_invn[row];
    float4 zv[4];
    const float4* zr = (const float4*)(z + (size_t)row * DDIM);
    #pragma unroll
    for (int t = 0; t < 4; t++) {
        float4 a = zr[lane * 4 + t];
        zv[t] = make_float4(a.x * inv, a.y * inv, a.z * inv, a.w * inv);
    }

    unsigned long long best = ~0ull;
    float bestdot = 0.0f;
    #pragma unroll 1
    for (int which = 0; which < 2; which++) {
        unsigned bal = which ? bal1 : bal0;
        unsigned long long kreg = which ? k1 : k0;
        while (bal) {
            int src = __ffs(bal) - 1;
            bal &= bal - 1;
            unsigned long long kk = __shfl_sync(0xffffffffu, kreg, src);
            const int idx = (int)(kk & 0xFFFFFFFFull);
            const float4* cr = (const float4*)(g_cb + (size_t)idx * DDIM);
            float p = 0.0f;
            #pragma unroll
            for (int t = 0; t < 4; t++) {
                float4 cv = cr[lane * 4 + t];
                p += zv[t].x * cv.x + zv[t].y * cv.y + zv[t].z * cv.z + zv[t].w * cv.w;
            }
            #pragma unroll
            for (int off = 16; off; off >>= 1) p += __shfl_xor_sync(0xffffffffu, p, off);
            unsigned long long ek = score_key(g_ncb[idx] - 2.0f * p, idx);
            if (ek < best) { best = ek; bestdot = p; }   // p warp-uniform after reduce
        }
    }

    // ---- fused projection: out_row = bestdot * cb[best] ----
    const int idx = (int)(best & 0xFFFFFFFFull);
    const float4* cw = (const float4*)(g_cb + (size_t)idx * DDIM);
    float4* ow = (float4*)(out + (size_t)row * DDIM);
    #pragma unroll
    for (int t = 0; t < 4; t++) {
        int j = t * 32 + lane;               // coalesced 128B per iteration
        float4 c = cw[j];
        ow[j] = make_float4(bestdot * c.x, bestdot * c.y, bestdot * c.z, bestdot * c.w);
    }
    if (lane == 0 && out_size >= NROWS * DDIM + NROWS)
        out[(size_t)NROWS * DDIM + row] = (float)idx;
}

extern "C" void kernel_launch(void* const* d_in, const int* in_sizes, int n_in,
                              void* d_out, int out_size) {
    const float* z   = (const float*)d_in[0];
    const float* emb = (const float*)d_in[1];
    if (n_in >= 2 && in_sizes[0] == KCODES * DDIM && in_sizes[1] == NROWS * DDIM) {
        const float* t = z; z = emb; emb = t;
    }

    cudaFuncSetAttribute(vq_mma_kernel, cudaFuncAttributeMaxDynamicSharedMemorySize, SMEM_TOTAL);

    normalize_z_kernel<<<NROWS, 128>>>(z);
    normalize_cb_kernel<<<KCODES, 128>>>(emb);

    dim3 grid(KCODES / TN, NROWS / TM);   // (32, 512)
    vq_mma_kernel<<<grid, NTHREADS, SMEM_TOTAL>>>();

    select_proj_kernel<<<NROWS / 8, 256>>>(z, (float*)d_out, out_size);
}